// round 2
// baseline (speedup 1.0000x reference)
#include <cuda_runtime.h>
#include <cuda_bf16.h>

#define T_LEN 4000
#define BLOCK 128
#define SEG 32          // outputs per thread (125 active threads per row)
#define W 24            // truncated EMA lookback taps: (1-s)^24 ~ 8e-6
#define SH_PAD(i) ((i) + ((i) >> 5))

__device__ __forceinline__ float fast_exp2(float x) {
    float y;
    asm("ex2.approx.ftz.f32 %0, %1;" : "=f"(y) : "f"(x));
    return y;
}
__device__ __forceinline__ float fast_log2(float x) {
    float y;
    asm("lg2.approx.ftz.f32 %0, %1;" : "=f"(y) : "f"(x));
    return y;
}

__global__ __launch_bounds__(BLOCK) void pcen_kernel(
    const float* __restrict__ x,
    const float* __restrict__ alpha_p,
    const float* __restrict__ delta_p,
    const float* __restrict__ r_p,
    float* __restrict__ out)
{
    __shared__ float sh[T_LEN + (T_LEN >> 5)];  // 4125 floats, padded layout

    const int row = blockIdx.x;
    const int tid = threadIdx.x;
    const float* __restrict__ xr = x + (size_t)row * T_LEN;
    float* __restrict__ outr = out + (size_t)row * T_LEN;

    // ---- stage the row into padded shared (coalesced float4 global loads) ----
    const float4* __restrict__ x4 = (const float4*)xr;
    #pragma unroll
    for (int i = tid; i < T_LEN / 4; i += BLOCK) {
        float4 v = x4[i];
        int b = i * 4;
        sh[SH_PAD(b + 0)] = v.x;
        sh[SH_PAD(b + 1)] = v.y;
        sh[SH_PAD(b + 2)] = v.z;
        sh[SH_PAD(b + 3)] = v.w;
    }

    // ---- scalar params (L1-broadcast loads) ----
    float alpha = fminf(fmaxf(alpha_p[0], 0.01f), 0.99f);
    float delta = fabsf(delta_p[0]) + 1e-6f;
    float r     = fminf(fmaxf(r_p[0], 0.01f), 1.0f);
    float dr    = fast_exp2(r * fast_log2(delta));   // delta^r (delta > 0)
    float nalpha = -alpha;

    __syncthreads();

    const float S   = 512.0f / 1323.0f;   // HOP/(SR*INIT_T), exact
    const float OMS = 1.0f - S;

    const int t0 = tid * SEG;
    float M = 0.0f;

    // ---- startup: reconstruct M at segment start via truncated window ----
    if (t0 < T_LEN) {
        if (t0 == 0) {
            M = sh[0];                    // exact init: M[0] = x[0]
        } else {
            // M(t0) ~= sum_{j=0}^{23} s*(1-s)^j * x[t0-j]
            // weights constant-fold -> FFMA with immediate (rt=1)
            float acc = 0.0f;
            float wj = S;
            #pragma unroll
            for (int j = 0; j < W; j++) {
                int t = t0 - j;
                acc += wj * sh[t + (t >> 5)];
                wj *= OMS;
            }
            M = acc;
        }
    }

    // All cross-thread window reads done before in-place overwrite below.
    __syncthreads();

    // ---- main loop: exact recurrence within segment; outputs in-place ----
    if (t0 < T_LEN) {
        const int base = t0 + (t0 >> 5);   // = tid*33, conflict-free stride
        #pragma unroll 8
        for (int j = 0; j < SEG; j++) {
            float xv = sh[base + j];
            if (j > 0)
                M = OMS * M + S * xv;
            // smooth^-1 = exp2(-alpha * log2(eps + M))
            float L    = fast_log2(1e-6f + M);
            float sinv = fast_exp2(nalpha * L);
            float bse  = fmaf(xv, sinv, delta);      // x/smooth + delta  (>0)
            float o    = fast_exp2(r * fast_log2(bse)) - dr;
            sh[base + j] = o;
        }
    }

    __syncthreads();

    // ---- coalesced writeback (float4) ----
    float4* __restrict__ o4 = (float4*)outr;
    #pragma unroll
    for (int i = tid; i < T_LEN / 4; i += BLOCK) {
        int b = i * 4;
        float4 v;
        v.x = sh[SH_PAD(b + 0)];
        v.y = sh[SH_PAD(b + 1)];
        v.z = sh[SH_PAD(b + 2)];
        v.w = sh[SH_PAD(b + 3)];
        o4[i] = v;
    }
}

extern "C" void kernel_launch(void* const* d_in, const int* in_sizes, int n_in,
                              void* d_out, int out_size) {
    const float* mel   = (const float*)d_in[0];
    const float* alpha = (const float*)d_in[1];
    const float* delta = (const float*)d_in[2];
    const float* r     = (const float*)d_in[3];
    float* out = (float*)d_out;

    int rows = out_size / T_LEN;   // 128*128 = 16384
    pcen_kernel<<<rows, BLOCK>>>(mel, alpha, delta, r, out);
}